// round 13
// baseline (speedup 1.0000x reference)
#include <cuda_runtime.h>
#include <stdint.h>

// Shapes (fixed by the problem)
#define B    8
#define C    256
#define HIN  64          // input spatial 64x64
#define S    (HIN*HIN)   // 4096
#define HO   256         // output spatial 256x256
#define K    21
#define EPSF 1e-6f

#define SPLIT  16        // s-range splits (4 y-rows per block)
#define CSPLIT 2         // channel splits (128 c per block) -> 2 CTA/SM
#define SRANGE (S/SPLIT) // 256 s per block
#define SCH    64        // s per feats smem chunk
#define NCH    (SRANGE/SCH)
#define FSTR   68        // padded row stride (floats): 272B, conflict-free float4
#define CB     (C/CSPLIT)

// smem layout (bytes):
//   [0, 43008)          Ws : resident W dup-pairs [K][SRANGE] u64
//   [43008, 112640)     Fs : feats double buffer [2][CB*FSTR] f32
//   Cs ([4][K][68] u16, 11424 B) aliases the buf1 region; dead before buf1 prefetch.
#define WS_BYTES  (K*SRANGE*8)            // 43008
#define FS_OFF    WS_BYTES
#define FS_BYTES  (CB*FSTR*4)             // 34816 per buffer
#define CS_OFF    (FS_OFF + FS_BYTES)     // 77824 (buf1 start)
#define SMEM_D    (WS_BYTES + 2*FS_BYTES) // 112640 B -> 2 CTA/SM

// ---------------- scratch (__device__ globals; no allocations) ----------------
__device__ unsigned g_rowcnt[B * K * HIN];        // exact 64*count per (b,k,y) row
__device__ float    g_sums[SPLIT * B * K * C];    // partial per-image per-class sums

__device__ __forceinline__ int bil_w8(int Yx, int r) {
    int t  = 2 * Yx - 3;
    int y0 = ((t + 8) >> 3) - 1;
    int f8 = (t + 8) & 7;
    int y0c = min(max(y0, 0), HIN - 1);
    int y1c = min(max(y0 + 1, 0), HIN - 1);
    int w = 0;
    if (y0c == r) w += 8 - f8;
    if (y1c == r) w += f8;
    return w;
}

__device__ __forceinline__ void fma2(uint64_t& d, uint64_t a, uint64_t b) {
    asm("fma.rn.f32x2 %0, %1, %2, %0;" : "+l"(d) : "l"(a), "l"(b));
}
__device__ __forceinline__ uint64_t add2(uint64_t a, uint64_t b) {
    uint64_t d; asm("add.rn.f32x2 %0, %1, %2;" : "=l"(d) : "l"(a), "l"(b)); return d;
}
__device__ __forceinline__ uint64_t pack2(float x, float y) {
    uint64_t r; asm("mov.b64 %0, {%1, %2};" : "=l"(r) : "f"(x), "f"(y)); return r;
}
__device__ __forceinline__ void unpack2(float& x, float& y, uint64_t a) {
    asm("mov.b64 {%0, %1}, %2;" : "=f"(x), "=f"(y) : "l"(a));
}
__device__ __forceinline__ void cp16(void* dst, const void* src) {
    unsigned u = (unsigned)__cvta_generic_to_shared(dst);
    asm volatile("cp.async.cg.shared.global [%0], [%1], 16;" :: "r"(u), "l"(src));
}

// no-op kernel: shifts ncu's -s 5 -c 1 capture onto kernD (pattern N,D,N,E)
__global__ void kernN() {}

// ---------------- Kernel D (fused): masks -> W (registers->smem) -> sums -----
// grid (SPLIT, CSPLIT, B), block 256 = 8 warps = 2 k-halves x 4 s-subranges.
// lane owns 4 channels {lane, +32, +64, +96}: each broadcast W-LDS.128 now
// feeds 4 FMA2 (was 2) -> W-LDS traffic halved. 22 u64 accumulators per lane
// over the warp's 11-k half; half-1 accumulates k=10 too but discards it.
extern "C" __global__ void __launch_bounds__(256, 2) kernD(
        const float* __restrict__ feats, const int* __restrict__ masks) {
    extern __shared__ unsigned char smem[];
    uint64_t* Ws = (uint64_t*)smem;                 // [K][SRANGE]
    float*    Fs = (float*)(smem + FS_OFF);         // [2][CB*FSTR]
    uint16_t* Cs = (uint16_t*)(smem + CS_OFF);      // [4][K][68]

    int split = blockIdx.x, cb = blockIdx.y, b = blockIdx.z;
    int tid = threadIdx.x, warp = tid >> 5, lane = tid & 31;
    int half = warp >> 2, sub = warp & 3;           // k-half x s-subrange
    int k0 = half ? 10 : 0;

    // ---- Prologue: direct 8x8 mask window, all-register (exact integers) ----
    {
        int x = tid & 63, yy = tid >> 6;
        int y = split * 4 + yy;

        unsigned wy8[8], wx8[8];
        int po[4];
        #pragma unroll
        for (int d = 0; d < 8; d++) {
            int Y = 4 * y - 2 + d;
            wy8[d] = (Y < 0 || Y >= HO) ? 0u : (unsigned)bil_w8(Y, y);
            int X = 4 * x - 2 + d;
            wx8[d] = (X < 0 || X >= HO) ? 0u : (unsigned)bil_w8(X, x);
        }
        #pragma unroll
        for (int j = 0; j < 4; j++)
            po[j] = min(max(4 * x - 2 + 2 * j, 0), HO - 2) >> 1;

        unsigned acc12[12];
        #pragma unroll
        for (int j = 0; j < 12; j++) acc12[j] = 0u;

        #pragma unroll
        for (int dy = 0; dy < 8; dy++) {
            unsigned wy = wy8[dy];
            if (wy == 0) continue;
            int Y = 4 * y - 2 + dy;
            const int2* row = (const int2*)(masks + ((size_t)b * HO + Y) * HO);
            uint64_t r0 = 0, r1 = 0, r2 = 0;
            #pragma unroll
            for (int j = 0; j < 4; j++) {
                int2 p = row[po[j]];
                #pragma unroll
                for (int h = 0; h < 2; h++) {
                    int lbl = h ? p.y : p.x;
                    unsigned wx = wx8[2 * j + h];
                    uint64_t a = (uint64_t)wx << ((lbl & 7) * 8);
                    a = ((unsigned)lbl < (unsigned)K) ? a : 0ull;
                    int s3 = lbl >> 3;
                    r0 += (s3 == 0) ? a : 0ull;
                    r1 += (s3 == 1) ? a : 0ull;
                    r2 += (s3 == 2) ? a : 0ull;
                }
            }
            unsigned v0 = (unsigned)r0, v1 = (unsigned)(r0 >> 32);
            unsigned v2 = (unsigned)r1, v3 = (unsigned)(r1 >> 32);
            unsigned v4 = (unsigned)r2, v5 = (unsigned)(r2 >> 32);
            acc12[0]  += __byte_perm(v0, 0, 0x4140) * wy;
            acc12[1]  += __byte_perm(v0, 0, 0x4342) * wy;
            acc12[2]  += __byte_perm(v1, 0, 0x4140) * wy;
            acc12[3]  += __byte_perm(v1, 0, 0x4342) * wy;
            acc12[4]  += __byte_perm(v2, 0, 0x4140) * wy;
            acc12[5]  += __byte_perm(v2, 0, 0x4342) * wy;
            acc12[6]  += __byte_perm(v3, 0, 0x4140) * wy;
            acc12[7]  += __byte_perm(v3, 0, 0x4342) * wy;
            acc12[8]  += __byte_perm(v4, 0, 0x4140) * wy;
            acc12[9]  += __byte_perm(v4, 0, 0x4342) * wy;
            acc12[10] += __byte_perm(v5, 0, 0x4140) * wy;
            acc12[11] += __byte_perm(v5, 0, 0x4342) * wy;
        }

        int sl = yy * HIN + x;
        #pragma unroll
        for (int k = 0; k < K; k++) {
            unsigned val = (acc12[k >> 1] >> ((k & 1) * 16)) & 0xFFFFu;
            float f = (float)val * (1.0f / 64.0f);
            Ws[k * SRANGE + sl] = pack2(f, f);
            Cs[(yy * K + k) * 68 + x] = (uint16_t)val;
        }
    }
    __syncthreads();

    const float* Fg = feats + ((size_t)b * C + cb * CB) * S;
    const int sbase0 = split * SRANGE;

    #define STAGE(BUF, SB) do {                                                   \
        for (int i = tid; i < CB * SCH / 4; i += 256) {                           \
            int c = i >> 4, j4 = i & 15;                                          \
            cp16(&Fs[(BUF) * CB * FSTR + c * FSTR + j4 * 4],                      \
                 Fg + (size_t)c * S + (SB) + j4 * 4);                             \
        }                                                                         \
        asm volatile("cp.async.commit_group;");                                   \
    } while (0)

    STAGE(0, sbase0);   // buf0; Cs (aliasing buf1) still live

    if (cb == 0 && tid < 4 * K) {
        int yy = tid & 3, k = tid >> 2;
        const uint16_t* cp = &Cs[(yy * K + k) * 68];
        unsigned t = 0;
        #pragma unroll 16
        for (int xx = 0; xx < HIN; xx++) t += (unsigned)cp[xx];
        g_rowcnt[(b * K + k) * HIN + split * 4 + yy] = t;
    }
    __syncthreads();   // Cs dead; buf1 free

    uint64_t acc[22];   // [0..10]: (c0,c1) per j ; [11..21]: (c2,c3) per j
    #pragma unroll
    for (int j = 0; j < 22; j++) acc[j] = 0ull;

    #pragma unroll 1
    for (int chunk = 0; chunk < NCH; chunk++) {
        if (chunk + 1 < NCH) {
            STAGE((chunk + 1) & 1, sbase0 + (chunk + 1) * SCH);
            asm volatile("cp.async.wait_group 1;");
        } else {
            asm volatile("cp.async.wait_group 0;");
        }
        __syncthreads();

        const float* fbase = &Fs[(chunk & 1) * CB * FSTR + lane * FSTR];
        #pragma unroll
        for (int i = 0; i < 16; i += 4) {
            int sc = sub * 16 + i;                 // within-chunk col
            float4 f0 = *(const float4*)&fbase[sc];
            float4 f1 = *(const float4*)&fbase[32 * FSTR + sc];
            float4 f2 = *(const float4*)&fbase[64 * FSTR + sc];
            float4 f3 = *(const float4*)&fbase[96 * FSTR + sc];
            uint64_t pAx = pack2(f0.x, f1.x), pBx = pack2(f2.x, f3.x);
            uint64_t pAy = pack2(f0.y, f1.y), pBy = pack2(f2.y, f3.y);
            uint64_t pAz = pack2(f0.z, f1.z), pBz = pack2(f2.z, f3.z);
            uint64_t pAw = pack2(f0.w, f1.w), pBw = pack2(f2.w, f3.w);
            int sw = chunk * SCH + sc;
            #pragma unroll
            for (int j = 0; j < 11; j++) {
                int k = k0 + j;
                ulonglong2 w01 = *(const ulonglong2*)&Ws[k * SRANGE + sw];       // broadcast
                ulonglong2 w23 = *(const ulonglong2*)&Ws[k * SRANGE + sw + 2];   // broadcast
                fma2(acc[j],      pAx, w01.x);  fma2(acc[j + 11], pBx, w01.x);
                fma2(acc[j],      pAy, w01.y);  fma2(acc[j + 11], pBy, w01.y);
                fma2(acc[j],      pAz, w23.x);  fma2(acc[j + 11], pBz, w23.x);
                fma2(acc[j],      pAw, w23.y);  fma2(acc[j + 11], pBw, w23.y);
            }
        }
        __syncthreads();   // protect feats buffer reuse
    }
    #undef STAGE

    // reduce 4 s-subrange warps within each k-half (Ws region now dead)
    uint64_t* red = (uint64_t*)smem;   // 4 warps x 22 x 32 u64 = 22528 B
    if (sub >= 2) {
        #pragma unroll
        for (int j = 0; j < 22; j++) red[((half * 2 + (sub - 2)) * 22 + j) * 32 + lane] = acc[j];
    }
    __syncthreads();
    if (sub < 2) {
        #pragma unroll
        for (int j = 0; j < 22; j++) acc[j] = add2(acc[j], red[((half * 2 + sub) * 22 + j) * 32 + lane]);
    }
    __syncthreads();
    if (sub == 1) {
        #pragma unroll
        for (int j = 0; j < 22; j++) red[(half * 22 + j) * 32 + lane] = acc[j];
    }
    __syncthreads();
    if (sub == 0) {
        float* outp = &g_sums[(((size_t)split * B + b) * K) * C];
        int cbase = cb * CB + lane;
        #pragma unroll
        for (int j = 0; j < 11; j++) {
            if (half && j == 0) continue;          // k=10 owned by half 0
            int k = k0 + j;
            uint64_t tA = add2(acc[j],      red[(half * 22 + j) * 32 + lane]);
            uint64_t tB = add2(acc[j + 11], red[(half * 22 + j + 11) * 32 + lane]);
            float a0, a1, a2, a3;
            unpack2(a0, a1, tA);
            unpack2(a2, a3, tB);
            outp[k * C + cbase]      = a0;
            outp[k * C + cbase + 32] = a1;
            outp[k * C + cbase + 64] = a2;
            outp[k * C + cbase + 96] = a3;
        }
    }
}

// ---------------- Kernel E: finalize prototypes ------------------------------
// grid (K, 8), block 256 = 8 warps (one per b) x 32 lanes (one channel each)
__global__ void kernE(float* __restrict__ out) {
    int k = blockIdx.x, cg = blockIdx.y;
    int tid = threadIdx.x, b = tid >> 5, lane = tid & 31;
    int c = cg * 32 + lane;

    float v = 0.f;
    #pragma unroll
    for (int sp = 0; sp < SPLIT; sp++)
        v += g_sums[((sp * B + b) * K + k) * C + c];

    const unsigned* rc = &g_rowcnt[(b * K + k) * HIN];
    unsigned cr = rc[lane] + rc[lane + 32];
    #pragma unroll
    for (int o = 16; o > 0; o >>= 1) cr += __shfl_xor_sync(0xFFFFFFFFu, cr, o);
    v *= 1.0f / ((float)cr * (1.0f / 64.0f) + EPSF);

    __shared__ float red[B][32];
    red[b][lane] = v;
    __syncthreads();
    if (b == 0) {
        float a = red[0][lane];
        #pragma unroll
        for (int w = 1; w < B; w++) a += red[w][lane];
        out[k * C + c] = a * (1.0f / (float)B);
    }
}

// ---------------- launch -----------------------------------------------------
extern "C" void kernel_launch(void* const* d_in, const int* in_sizes, int n_in,
                              void* d_out, int out_size) {
    const float* feats = (const float*)d_in[0];   // [8,256,64,64]
    const int*   masks = (const int*)d_in[1];     // [8,256,256]
    float*       out   = (float*)d_out;           // [21,256]

    cudaFuncSetAttribute(kernD, cudaFuncAttributeMaxDynamicSharedMemorySize, SMEM_D);

    // pattern N,D,N,E: ncu's "-s 5 -c 1" (6th launch) lands on kernD
    kernN<<<1, 32>>>();
    kernD<<<dim3(SPLIT, CSPLIT, B), 256, SMEM_D>>>(feats, masks);
    kernN<<<1, 32>>>();
    kernE<<<dim3(K, 8), 256>>>(out);
}

// round 14
// speedup vs baseline: 1.0606x; 1.0606x over previous
#include <cuda_runtime.h>
#include <stdint.h>

// Shapes (fixed by the problem)
#define B    8
#define C    256
#define HIN  64          // input spatial 64x64
#define S    (HIN*HIN)   // 4096
#define HO   256         // output spatial 256x256
#define K    21
#define EPSF 1e-6f

#define SPLIT   16            // s-range splits (4 y-rows per block)
#define SRANGE  (S/SPLIT)     // 256 s per block
#define SCH     64            // s per feats smem chunk
#define NCH     (SRANGE/SCH)  // 4
#define FSTR    68            // padded row stride (floats): 272B, conflict-free
#define NCTA    (SPLIT*B)     // 128 CTAs <= 148 SMs: all co-resident at occ 1

// smem layout (dynamic):
//   [0, 43008)       Ws : resident W dup-pairs [K][SRANGE] u64
//   [43008, 54432)   Cs : counts [4][K][68] u16
//   [54528, 193792)  Fs : feats double buffer [2][C][FSTR] f32
#define WS_BYTES (K*SRANGE*8)                       // 43008
#define CS_OFF   WS_BYTES
#define CS_BYTES (4*K*68*2)                         // 11424
#define FS_OFF   ((CS_OFF + CS_BYTES + 127) & ~127) // 54528
#define FS_BYTES (C*FSTR*4)                         // 69632
#define SMEM_D   (FS_OFF + 2*FS_BYTES)              // 193792 -> occ 1 FORCED

// ---------------- scratch (__device__ globals; zero-init at load) -------------
__device__ unsigned g_rowcnt[B * K * HIN];        // exact 64*count per (b,k,y)
__device__ float    g_sums[SPLIT * B * K * C];    // partial per-class sums
__device__ unsigned g_ctr;                        // monotonic epoch counter

__device__ __forceinline__ int bil_w8(int Yx, int r) {
    int t  = 2 * Yx - 3;
    int y0 = ((t + 8) >> 3) - 1;
    int f8 = (t + 8) & 7;
    int y0c = min(max(y0, 0), HIN - 1);
    int y1c = min(max(y0 + 1, 0), HIN - 1);
    int w = 0;
    if (y0c == r) w += 8 - f8;
    if (y1c == r) w += f8;
    return w;
}

__device__ __forceinline__ void fma2(uint64_t& d, uint64_t a, uint64_t b) {
    asm("fma.rn.f32x2 %0, %1, %2, %0;" : "+l"(d) : "l"(a), "l"(b));
}
__device__ __forceinline__ uint64_t add2(uint64_t a, uint64_t b) {
    uint64_t d; asm("add.rn.f32x2 %0, %1, %2;" : "=l"(d) : "l"(a), "l"(b)); return d;
}
__device__ __forceinline__ uint64_t pack2(float x, float y) {
    uint64_t r; asm("mov.b64 %0, {%1, %2};" : "=l"(r) : "f"(x), "f"(y)); return r;
}
__device__ __forceinline__ void unpack2(float& x, float& y, uint64_t a) {
    asm("mov.b64 {%0, %1}, %2;" : "=f"(x), "=f"(y) : "l"(a));
}
__device__ __forceinline__ void cp16(void* dst, const void* src) {
    unsigned u = (unsigned)__cvta_generic_to_shared(dst);
    asm volatile("cp.async.cg.shared.global [%0], [%1], 16;" :: "r"(u), "l"(src));
}

// ---------------- THE kernel: masks -> W -> sums -> barrier -> prototypes ----
// grid (SPLIT, 1, B) = 128 CTAs, 512 threads, 194KB smem (occ 1 forced).
// warps 0-7: register mask-prologue (exact integer W); warps 8-15: concurrent
// cp.async prefetch of feats chunks 0+1. Mainloop: all 16 warps =
// (k-half x cgroup x 4 s-subranges); lane owns channels {cg*128+lane,+32,+64,+96}.
// Epilogue: deadlock-free grid barrier (128 co-resident CTAs, monotonic epoch),
// then fused finalization.
extern "C" __global__ void __launch_bounds__(512, 1) kernD(
        const float* __restrict__ feats, const int* __restrict__ masks,
        float* __restrict__ out) {
    extern __shared__ unsigned char smem[];
    uint64_t* Ws = (uint64_t*)smem;                 // [K][SRANGE]
    uint16_t* Cs = (uint16_t*)(smem + CS_OFF);      // [4][K][68]
    float*    Fs = (float*)(smem + FS_OFF);         // [2][C][FSTR]

    int split = blockIdx.x, b = blockIdx.z;
    int flat = b * SPLIT + split;                   // 0..127
    int tid = threadIdx.x, warp = tid >> 5, lane = tid & 31;
    int half = warp >> 3, cg = (warp >> 2) & 1, sub = warp & 3;
    int k0 = half ? 10 : 0;

    const float* Fg = feats + (size_t)b * C * S;
    const int sbase0 = split * SRANGE;

    if (tid < 256) {
        // ---- Prologue: direct 8x8 mask window, all-register, exact ints ----
        int x = tid & 63, yy = tid >> 6;
        int y = split * 4 + yy;

        unsigned wy8[8], wx8[8];
        int po[4];
        #pragma unroll
        for (int d = 0; d < 8; d++) {
            int Y = 4 * y - 2 + d;
            wy8[d] = (Y < 0 || Y >= HO) ? 0u : (unsigned)bil_w8(Y, y);
            int X = 4 * x - 2 + d;
            wx8[d] = (X < 0 || X >= HO) ? 0u : (unsigned)bil_w8(X, x);
        }
        #pragma unroll
        for (int j = 0; j < 4; j++)
            po[j] = min(max(4 * x - 2 + 2 * j, 0), HO - 2) >> 1;

        unsigned acc12[12];
        #pragma unroll
        for (int j = 0; j < 12; j++) acc12[j] = 0u;

        #pragma unroll
        for (int dy = 0; dy < 8; dy++) {
            unsigned wy = wy8[dy];
            if (wy == 0) continue;                  // warp-uniform (boundary)
            int Y = 4 * y - 2 + dy;
            const int2* row = (const int2*)(masks + ((size_t)b * HO + Y) * HO);
            uint64_t r0 = 0, r1 = 0, r2 = 0;
            #pragma unroll
            for (int j = 0; j < 4; j++) {
                int2 p = row[po[j]];
                #pragma unroll
                for (int h = 0; h < 2; h++) {
                    int lbl = h ? p.y : p.x;
                    unsigned wx = wx8[2 * j + h];
                    uint64_t a = (uint64_t)wx << ((lbl & 7) * 8);
                    a = ((unsigned)lbl < (unsigned)K) ? a : 0ull;
                    int s3 = lbl >> 3;
                    r0 += (s3 == 0) ? a : 0ull;
                    r1 += (s3 == 1) ? a : 0ull;
                    r2 += (s3 == 2) ? a : 0ull;
                }
            }
            unsigned v0 = (unsigned)r0, v1 = (unsigned)(r0 >> 32);
            unsigned v2 = (unsigned)r1, v3 = (unsigned)(r1 >> 32);
            unsigned v4 = (unsigned)r2, v5 = (unsigned)(r2 >> 32);
            acc12[0]  += __byte_perm(v0, 0, 0x4140) * wy;
            acc12[1]  += __byte_perm(v0, 0, 0x4342) * wy;
            acc12[2]  += __byte_perm(v1, 0, 0x4140) * wy;
            acc12[3]  += __byte_perm(v1, 0, 0x4342) * wy;
            acc12[4]  += __byte_perm(v2, 0, 0x4140) * wy;
            acc12[5]  += __byte_perm(v2, 0, 0x4342) * wy;
            acc12[6]  += __byte_perm(v3, 0, 0x4140) * wy;
            acc12[7]  += __byte_perm(v3, 0, 0x4342) * wy;
            acc12[8]  += __byte_perm(v4, 0, 0x4140) * wy;
            acc12[9]  += __byte_perm(v4, 0, 0x4342) * wy;
            acc12[10] += __byte_perm(v5, 0, 0x4140) * wy;
            acc12[11] += __byte_perm(v5, 0, 0x4342) * wy;
        }

        int sl = yy * HIN + x;
        #pragma unroll
        for (int k = 0; k < K; k++) {
            unsigned val = (acc12[k >> 1] >> ((k & 1) * 16)) & 0xFFFFu;
            float f = (float)val * (1.0f / 64.0f);
            Ws[k * SRANGE + sl] = pack2(f, f);
            Cs[(yy * K + k) * 68 + x] = (uint16_t)val;
        }
    } else {
        // ---- Concurrent prefetch of feats chunks 0 and 1 (warps 8-15) ----
        int t = tid - 256;
        for (int i = t; i < C * SCH / 4; i += 256) {
            int c = i >> 4, j4 = i & 15;
            cp16(&Fs[c * FSTR + j4 * 4], Fg + (size_t)c * S + sbase0 + j4 * 4);
        }
        asm volatile("cp.async.commit_group;");
        for (int i = t; i < C * SCH / 4; i += 256) {
            int c = i >> 4, j4 = i & 15;
            cp16(&Fs[C * FSTR + c * FSTR + j4 * 4],
                 Fg + (size_t)c * S + sbase0 + SCH + j4 * 4);
        }
        asm volatile("cp.async.commit_group;");
    }
    __syncthreads();   // Ws, Cs valid

    // exact integer row counts (one CTA per (split,b); no atomics)
    if (tid < 4 * K) {
        int yy = tid & 3, k = tid >> 2;
        const uint16_t* cp = &Cs[(yy * K + k) * 68];
        unsigned t = 0;
        #pragma unroll 16
        for (int xx = 0; xx < HIN; xx++) t += (unsigned)cp[xx];
        g_rowcnt[(b * K + k) * HIN + split * 4 + yy] = t;
    }

    uint64_t acc[22];   // [0..10]: (c0,c1) per j ; [11..21]: (c2,c3) per j
    #pragma unroll
    for (int j = 0; j < 22; j++) acc[j] = 0ull;

    #pragma unroll 1
    for (int chunk = 0; chunk < NCH; chunk++) {
        if (chunk == NCH - 1) asm volatile("cp.async.wait_group 0;");
        else                  asm volatile("cp.async.wait_group 1;");
        __syncthreads();

        const float* fbase = &Fs[(chunk & 1) * C * FSTR + (cg * 128 + lane) * FSTR];
        #pragma unroll
        for (int i = 0; i < 16; i += 4) {
            int sc = sub * 16 + i;
            float4 f0 = *(const float4*)&fbase[sc];
            float4 f1 = *(const float4*)&fbase[32 * FSTR + sc];
            float4 f2 = *(const float4*)&fbase[64 * FSTR + sc];
            float4 f3 = *(const float4*)&fbase[96 * FSTR + sc];
            uint64_t pAx = pack2(f0.x, f1.x), pBx = pack2(f2.x, f3.x);
            uint64_t pAy = pack2(f0.y, f1.y), pBy = pack2(f2.y, f3.y);
            uint64_t pAz = pack2(f0.z, f1.z), pBz = pack2(f2.z, f3.z);
            uint64_t pAw = pack2(f0.w, f1.w), pBw = pack2(f2.w, f3.w);
            int sw = chunk * SCH + sc;
            #pragma unroll
            for (int j = 0; j < 11; j++) {
                int k = k0 + j;
                ulonglong2 w01 = *(const ulonglong2*)&Ws[k * SRANGE + sw];       // broadcast
                ulonglong2 w23 = *(const ulonglong2*)&Ws[k * SRANGE + sw + 2];   // broadcast
                fma2(acc[j],      pAx, w01.x);  fma2(acc[j + 11], pBx, w01.x);
                fma2(acc[j],      pAy, w01.y);  fma2(acc[j + 11], pBy, w01.y);
                fma2(acc[j],      pAz, w23.x);  fma2(acc[j + 11], pBz, w23.x);
                fma2(acc[j],      pAw, w23.y);  fma2(acc[j + 11], pBw, w23.y);
            }
        }
        __syncthreads();
        if (chunk + 2 < NCH) {
            int sb = sbase0 + (chunk + 2) * SCH;
            for (int i = tid; i < C * SCH / 4; i += 512) {
                int c = i >> 4, j4 = i & 15;
                cp16(&Fs[(chunk & 1) * C * FSTR + c * FSTR + j4 * 4],
                     Fg + (size_t)c * S + sb + j4 * 4);
            }
            asm volatile("cp.async.commit_group;");
        }
    }

    // ---- reduce 4 s-subrange warps per (half,cg) group (Ws/Cs now dead) ----
    int gc = half * 2 + cg;
    uint64_t* red = (uint64_t*)smem;   // 4 groups x 2 x 22 x 32 u64 = 45056 B
    if (sub >= 2) {
        #pragma unroll
        for (int j = 0; j < 22; j++) red[((gc * 2 + (sub - 2)) * 22 + j) * 32 + lane] = acc[j];
    }
    __syncthreads();
    if (sub < 2) {
        #pragma unroll
        for (int j = 0; j < 22; j++) acc[j] = add2(acc[j], red[((gc * 2 + sub) * 22 + j) * 32 + lane]);
    }
    __syncthreads();
    if (sub == 1) {
        #pragma unroll
        for (int j = 0; j < 22; j++) red[(gc * 22 + j) * 32 + lane] = acc[j];
    }
    __syncthreads();
    if (sub == 0) {
        float* outp = &g_sums[(((size_t)split * B + b) * K) * C];
        int cbase = cg * 128 + lane;
        #pragma unroll
        for (int j = 0; j < 11; j++) {
            if (half && j == 0) continue;          // k=10 owned by half 0
            int k = k0 + j;
            uint64_t tA = add2(acc[j],      red[(gc * 22 + j) * 32 + lane]);
            uint64_t tB = add2(acc[j + 11], red[(gc * 22 + j + 11) * 32 + lane]);
            float a0, a1, a2, a3;
            unpack2(a0, a1, tA);
            unpack2(a2, a3, tB);
            outp[k * C + cbase]      = a0;
            outp[k * C + cbase + 32] = a1;
            outp[k * C + cbase + 64] = a2;
            outp[k * C + cbase + 96] = a3;
        }
    }

    // ---- grid barrier: 128 CTAs all co-resident (occ-1 forced) -> safe ----
    __shared__ unsigned s_my;
    __threadfence();
    __syncthreads();                               // all g_sums/rowcnt fenced
    if (tid == 0) s_my = atomicAdd(&g_ctr, 1u);
    __syncthreads();
    unsigned target = (s_my / (unsigned)NCTA + 1u) * (unsigned)NCTA;
    if (tid == 0) {
        while (atomicAdd(&g_ctr, 0u) < target) __nanosleep(128);
    }
    __syncthreads();

    // ---- fused finalization (was kernE): 168 virtual blocks over 128 CTAs --
    __shared__ float redf[B][32];
    for (int vb = flat; vb < K * 8; vb += NCTA) {
        if (tid < 256) {
            int k = vb >> 3, cg8 = vb & 7;
            int eb = tid >> 5;                     // b
            int c = cg8 * 32 + lane;
            float v = 0.f;
            #pragma unroll
            for (int sp = 0; sp < SPLIT; sp++)
                v += __ldcg(&g_sums[((sp * B + eb) * K + k) * C + c]);
            const unsigned* rc = &g_rowcnt[(eb * K + k) * HIN];
            unsigned cr = __ldcg(&rc[lane]) + __ldcg(&rc[lane + 32]);
            #pragma unroll
            for (int o = 16; o > 0; o >>= 1) cr += __shfl_xor_sync(0xFFFFFFFFu, cr, o);
            v *= 1.0f / ((float)cr * (1.0f / 64.0f) + EPSF);
            redf[eb][lane] = v;
        }
        __syncthreads();
        if (tid < 32) {
            int k = vb >> 3, cg8 = vb & 7;
            float a = redf[0][lane];
            #pragma unroll
            for (int w = 1; w < B; w++) a += redf[w][lane];
            out[k * C + cg8 * 32 + lane] = a * (1.0f / (float)B);
        }
        __syncthreads();
    }
}

// ---------------- launch -----------------------------------------------------
extern "C" void kernel_launch(void* const* d_in, const int* in_sizes, int n_in,
                              void* d_out, int out_size) {
    const float* feats = (const float*)d_in[0];   // [8,256,64,64]
    const int*   masks = (const int*)d_in[1];     // [8,256,256]
    float*       out   = (float*)d_out;           // [21,256]

    cudaFuncSetAttribute(kernD, cudaFuncAttributeMaxDynamicSharedMemorySize, SMEM_D);

    kernD<<<dim3(SPLIT, 1, B), 512, SMEM_D>>>(feats, masks, out);
}